// round 4
// baseline (speedup 1.0000x reference)
#include <cuda_runtime.h>
#include <cstdint>

#define B_   16
#define L1_  1024
#define L2_  1024
#define DIN_ 1024
#define H_   16
#define DK_  64
#define DV_  64

// ---------------- scratch (allocation-free rule: __device__ globals) ----------------
__device__ float g_Q[B_ * L1_ * H_ * DK_];   // 64 MB, [b*L1+q][h*64+d]
__device__ float g_K[B_ * L2_ * H_ * DK_];   // 64 MB
__device__ float g_V[B_ * L2_ * H_ * DV_];   // 64 MB
__device__ unsigned char g_mask_c[B_ * L2_]; // canonical mask, 1 = masked

// ---------------- helpers ----------------
__device__ __forceinline__ unsigned f2tf(float f) {
    unsigned r;
    asm("cvt.rna.tf32.f32 %0, %1;" : "=r"(r) : "f"(f));
    return r;
}
__device__ __forceinline__ float f2tf_f(float f) { return __uint_as_float(f2tf(f)); }

// D(16x8) += A(16x8,tf32) * B(8x8,tf32), fp32 accum
__device__ __forceinline__ void mma8(float* d, const unsigned* a, unsigned b0, unsigned b1) {
    asm volatile(
        "mma.sync.aligned.m16n8k8.row.col.f32.tf32.tf32.f32 "
        "{%0,%1,%2,%3}, {%4,%5,%6,%7}, {%8,%9}, {%0,%1,%2,%3};\n"
        : "+f"(d[0]), "+f"(d[1]), "+f"(d[2]), "+f"(d[3])
        : "r"(a[0]), "r"(a[1]), "r"(a[2]), "r"(a[3]), "r"(b0), "r"(b1));
}

// ---------------- mask canonicalization ----------------
// y_mask is a bool array; harness byte encoding unknown (u8 / i32 / f32).
// Detect from data: any byte >1 => f32; nonzero byte at pos%4!=0 => u8; else i32.
__global__ void mask_canon_kernel(const unsigned char* __restrict__ m) {
    __shared__ int offnz, weird;
    if (threadIdx.x == 0) { offnz = 0; weird = 0; }
    __syncthreads();
    for (int i = threadIdx.x; i < 4096; i += 256) {
        unsigned char v = m[i];
        if (v > 1) atomicAdd(&weird, 1);
        else if (v && (i & 3)) atomicAdd(&offnz, 1);
    }
    __syncthreads();
    const int n = B_ * L2_;
    if (weird) {
        const float* f = (const float*)m;
        for (int i = threadIdx.x; i < n; i += 256) g_mask_c[i] = (f[i] != 0.0f) ? 1 : 0;
    } else if (offnz) {
        for (int i = threadIdx.x; i < n; i += 256) g_mask_c[i] = m[i] ? 1 : 0;
    } else {
        const int* mi = (const int*)m;
        for (int i = threadIdx.x; i < n; i += 256) g_mask_c[i] = mi[i] ? 1 : 0;
    }
}

// ---------------- projection GEMM: C[16384,1024] = X[16384,1024]@W[1024,1024] + bias ----------------
// Block tile 128x128, k-tile 16, 8 warps (2m x 4n), warp tile 64x32, m16n8k8 tf32.
// As[m][k] stride 20 and Bs[k][n] stride 136: fragment LDS bank-conflict-free.
__global__ __launch_bounds__(256, 2)
void proj_kernel(const float* __restrict__ X, const float* __restrict__ W,
                 const float* __restrict__ bias, float* __restrict__ C) {
    constexpr int N = H_ * DK_;  // 1024
    constexpr int K = DIN_;      // 1024
    __shared__ __align__(16) float As[128][20];
    __shared__ __align__(16) float Bs[16][136];

    const int tid  = threadIdx.x;
    const int lane = tid & 31;
    const int warp = tid >> 5;
    const int g  = lane >> 2, tg = lane & 3;
    const int wm = warp >> 2, wn = warp & 3;
    const int bm = blockIdx.y * 128, bn = blockIdx.x * 128;

    float acc[4][4][4];
#pragma unroll
    for (int i = 0; i < 4; i++)
#pragma unroll
        for (int j = 0; j < 4; j++)
#pragma unroll
            for (int r = 0; r < 4; r++) acc[i][j][r] = 0.f;

    for (int kt = 0; kt < K / 16; kt++) {
        float4 xa[2], wb[2];
#pragma unroll
        for (int i = 0; i < 2; i++) {
            int f = tid + 256 * i;
            int r = f >> 2, q = (f & 3) * 4;                       // A: 128 rows x 16 cols
            xa[i] = *(const float4*)&X[(size_t)(bm + r) * K + kt * 16 + q];
            int kk = f >> 5, n = (f & 31) * 4;                     // B: 16 rows x 128 cols
            wb[i] = *(const float4*)&W[(size_t)(kt * 16 + kk) * N + bn + n];
        }
        __syncthreads();  // prior iter's compute done before overwrite
#pragma unroll
        for (int i = 0; i < 2; i++) {
            int f = tid + 256 * i;
            int r = f >> 2, q = (f & 3) * 4;
            float4 t = make_float4(f2tf_f(xa[i].x), f2tf_f(xa[i].y), f2tf_f(xa[i].z), f2tf_f(xa[i].w));
            *(float4*)&As[r][q] = t;
            int kk = f >> 5, n = (f & 31) * 4;
            float4 u = make_float4(f2tf_f(wb[i].x), f2tf_f(wb[i].y), f2tf_f(wb[i].z), f2tf_f(wb[i].w));
            *(float4*)&Bs[kk][n] = u;
        }
        __syncthreads();
#pragma unroll
        for (int ks = 0; ks < 2; ks++) {
            unsigned a[4][4], bf[4][2];
#pragma unroll
            for (int mt = 0; mt < 4; mt++) {
                int m0 = wm * 64 + mt * 16;
                int c  = ks * 8 + tg;
                a[mt][0] = __float_as_uint(As[m0 + g][c]);
                a[mt][1] = __float_as_uint(As[m0 + g + 8][c]);
                a[mt][2] = __float_as_uint(As[m0 + g][c + 4]);
                a[mt][3] = __float_as_uint(As[m0 + g + 8][c + 4]);
            }
#pragma unroll
            for (int nt = 0; nt < 4; nt++) {
                int n0 = wn * 32 + nt * 8 + g;
                bf[nt][0] = __float_as_uint(Bs[ks * 8 + tg][n0]);
                bf[nt][1] = __float_as_uint(Bs[ks * 8 + tg + 4][n0]);
            }
#pragma unroll
            for (int mt = 0; mt < 4; mt++)
#pragma unroll
                for (int nt = 0; nt < 4; nt++)
                    mma8(acc[mt][nt], a[mt], bf[nt][0], bf[nt][1]);
        }
    }
    // epilogue: + bias, fp32 store
#pragma unroll
    for (int mt = 0; mt < 4; mt++) {
        int r0 = bm + wm * 64 + mt * 16 + g;
#pragma unroll
        for (int nt = 0; nt < 4; nt++) {
            int c = bn + wn * 32 + nt * 8 + 2 * tg;
            float b0 = bias[c], b1 = bias[c + 1];
            *(float2*)&C[(size_t)r0 * N + c]       = make_float2(acc[mt][nt][0] + b0, acc[mt][nt][1] + b1);
            *(float2*)&C[(size_t)(r0 + 8) * N + c] = make_float2(acc[mt][nt][2] + b0, acc[mt][nt][3] + b1);
        }
    }
}

// ---------------- flash attention ----------------
// Grid (8 q-tiles, H, B). 256 threads = 8 warps; warp w owns q rows [w*16, w*16+16).
// Per kv-tile of 128: S = Q@K^T (tf32 mma), online softmax in regs, P -> SMEM (tf32),
// O += P@V (tf32 mma). SMEM strides 68/72/132 keep all fragment LDS conflict-free.
#define KS_STRIDE 68
#define VS_STRIDE 72
#define PS_STRIDE 132
#define ATTN_SMEM_FLOATS (128 * KS_STRIDE + 128 * VS_STRIDE + 128 * PS_STRIDE + 128)
#define ATTN_SMEM_BYTES  (ATTN_SMEM_FLOATS * 4)

__global__ __launch_bounds__(256, 1)
void attn_kernel(const float* __restrict__ Qm, const float* __restrict__ Km,
                 const float* __restrict__ Vm, float* __restrict__ Out) {
    extern __shared__ __align__(16) float sm[];
    float* Ks   = sm;                                  // [128][68]
    float* Vs   = Ks + 128 * KS_STRIDE;                // [128][72]
    float* Ps   = Vs + 128 * VS_STRIDE;                // [128][132]
    float* mAdd = Ps + 128 * PS_STRIDE;                // [128]

    const int tid  = threadIdx.x;
    const int lane = tid & 31;
    const int warp = tid >> 5;
    const int g  = lane >> 2, tg = lane & 3;
    const int b  = blockIdx.z, h = blockIdx.y, q0 = blockIdx.x * 128;

    // Q A-fragments in registers (tf32), 16 rows x 64 cols per warp
    unsigned aq[8][4];
    {
        const float* qb = Qm + (size_t)(b * L1_ + q0 + warp * 16) * (H_ * DK_) + h * DK_;
#pragma unroll
        for (int kk = 0; kk < 8; kk++) {
            int c = kk * 8 + tg;
            aq[kk][0] = f2tf(qb[(size_t)g * (H_ * DK_) + c]);
            aq[kk][1] = f2tf(qb[(size_t)(g + 8) * (H_ * DK_) + c]);
            aq[kk][2] = f2tf(qb[(size_t)g * (H_ * DK_) + c + 4]);
            aq[kk][3] = f2tf(qb[(size_t)(g + 8) * (H_ * DK_) + c + 4]);
        }
    }

    float oacc[8][4];
#pragma unroll
    for (int i = 0; i < 8; i++)
#pragma unroll
        for (int r = 0; r < 4; r++) oacc[i][r] = 0.f;
    float m0 = -1e30f, m1 = -1e30f, l0 = 0.f, l1 = 0.f;

    float* prow0 = &Ps[(size_t)(warp * 16 + g) * PS_STRIDE];
    float* prow1 = &Ps[(size_t)(warp * 16 + g + 8) * PS_STRIDE];

    for (int jt = 0; jt < L2_ / 128; jt++) {
        const int j0 = jt * 128;
        __syncthreads();  // everyone done reading Ks/Vs/mAdd from prior iter
        // ---- cooperative fill of K,V tiles (convert to tf32) + mask ----
        {
            const float* kb = Km + (size_t)(b * L2_ + j0) * (H_ * DK_) + h * DK_;
            const float* vb = Vm + (size_t)(b * L2_ + j0) * (H_ * DV_) + h * DV_;
#pragma unroll
            for (int i = 0; i < 8; i++) {
                int f = tid + i * 256;          // 0..2047
                int r = f >> 4, dq = (f & 15) * 4;
                float4 kv = *(const float4*)&kb[(size_t)r * (H_ * DK_) + dq];
                float4 vv = *(const float4*)&vb[(size_t)r * (H_ * DV_) + dq];
                float4 kc = make_float4(f2tf_f(kv.x), f2tf_f(kv.y), f2tf_f(kv.z), f2tf_f(kv.w));
                float4 vc = make_float4(f2tf_f(vv.x), f2tf_f(vv.y), f2tf_f(vv.z), f2tf_f(vv.w));
                *(float4*)&Ks[(size_t)r * KS_STRIDE + dq] = kc;
                *(float4*)&Vs[(size_t)r * VS_STRIDE + dq] = vc;
            }
            if (tid < 128) mAdd[tid] = g_mask_c[b * L2_ + j0 + tid] ? -1e30f : 0.f;
        }
        __syncthreads();

        // ---- S = Q @ K^T : warp computes 16x128 scores ----
        float sacc[16][4];
#pragma unroll
        for (int nt = 0; nt < 16; nt++)
#pragma unroll
            for (int r = 0; r < 4; r++) sacc[nt][r] = 0.f;
#pragma unroll
        for (int kk = 0; kk < 8; kk++) {
#pragma unroll
            for (int nt = 0; nt < 16; nt++) {
                unsigned b0 = __float_as_uint(Ks[(size_t)(nt * 8 + g) * KS_STRIDE + kk * 8 + tg]);
                unsigned b1 = __float_as_uint(Ks[(size_t)(nt * 8 + g) * KS_STRIDE + kk * 8 + tg + 4]);
                mma8(sacc[nt], aq[kk], b0, b1);
            }
        }

        // ---- scale + mask + online softmax ----
        float tm0 = -1e30f, tm1 = -1e30f;
#pragma unroll
        for (int nt = 0; nt < 16; nt++) {
            int c0 = nt * 8 + 2 * tg;
            float ma = mAdd[c0], mb = mAdd[c0 + 1];
            sacc[nt][0] = sacc[nt][0] * 0.125f + ma;
            sacc[nt][1] = sacc[nt][1] * 0.125f + mb;
            sacc[nt][2] = sacc[nt][2] * 0.125f + ma;
            sacc[nt][3] = sacc[nt][3] * 0.125f + mb;
            tm0 = fmaxf(tm0, fmaxf(sacc[nt][0], sacc[nt][1]));
            tm1 = fmaxf(tm1, fmaxf(sacc[nt][2], sacc[nt][3]));
        }
        tm0 = fmaxf(tm0, __shfl_xor_sync(0xffffffffu, tm0, 1));
        tm0 = fmaxf(tm0, __shfl_xor_sync(0xffffffffu, tm0, 2));
        tm1 = fmaxf(tm1, __shfl_xor_sync(0xffffffffu, tm1, 1));
        tm1 = fmaxf(tm1, __shfl_xor_sync(0xffffffffu, tm1, 2));

        float mn0 = fmaxf(m0, tm0), mn1 = fmaxf(m1, tm1);
        float sc0 = __expf(m0 - mn0), sc1 = __expf(m1 - mn1);
        m0 = mn0; m1 = mn1;
        l0 *= sc0; l1 *= sc1;
#pragma unroll
        for (int nt = 0; nt < 8; nt++) {
            oacc[nt][0] *= sc0; oacc[nt][1] *= sc0;
            oacc[nt][2] *= sc1; oacc[nt][3] *= sc1;
        }
        // P = exp(S - m), masked -> 0; write to SMEM as tf32 (own warp rows only)
#pragma unroll
        for (int nt = 0; nt < 16; nt++) {
            int c0 = nt * 8 + 2 * tg;
            float p0 = (sacc[nt][0] > -1e29f) ? __expf(sacc[nt][0] - mn0) : 0.f;
            float p1 = (sacc[nt][1] > -1e29f) ? __expf(sacc[nt][1] - mn0) : 0.f;
            float p2 = (sacc[nt][2] > -1e29f) ? __expf(sacc[nt][2] - mn1) : 0.f;
            float p3 = (sacc[nt][3] > -1e29f) ? __expf(sacc[nt][3] - mn1) : 0.f;
            l0 += p0 + p1;
            l1 += p2 + p3;
            *(float2*)&prow0[c0] = make_float2(f2tf_f(p0), f2tf_f(p1));
            *(float2*)&prow1[c0] = make_float2(f2tf_f(p2), f2tf_f(p3));
        }
        __syncwarp();  // cross-lane SMEM RAW within warp

        // ---- O += P @ V ----
#pragma unroll
        for (int kk = 0; kk < 16; kk++) {
            unsigned ap[4];
            int c = kk * 8 + tg;
            ap[0] = __float_as_uint(prow0[c]);
            ap[1] = __float_as_uint(prow1[c]);
            ap[2] = __float_as_uint(prow0[c + 4]);
            ap[3] = __float_as_uint(prow1[c + 4]);
#pragma unroll
            for (int nt = 0; nt < 8; nt++) {
                unsigned b0 = __float_as_uint(Vs[(size_t)(kk * 8 + tg) * VS_STRIDE + nt * 8 + g]);
                unsigned b1 = __float_as_uint(Vs[(size_t)(kk * 8 + tg + 4) * VS_STRIDE + nt * 8 + g]);
                mma8(oacc[nt], ap, b0, b1);
            }
        }
    }

    // ---- finalize: reduce l across quad, normalize, store ----
    l0 += __shfl_xor_sync(0xffffffffu, l0, 1);
    l0 += __shfl_xor_sync(0xffffffffu, l0, 2);
    l1 += __shfl_xor_sync(0xffffffffu, l1, 1);
    l1 += __shfl_xor_sync(0xffffffffu, l1, 2);
    float r0 = 1.f / l0, r1 = 1.f / l1;

    size_t orow0 = (size_t)(b * L1_ + q0 + warp * 16 + g) * (H_ * DV_) + h * DV_;
    size_t orow1 = orow0 + (size_t)8 * (H_ * DV_);
#pragma unroll
    for (int nt = 0; nt < 8; nt++) {
        int c = nt * 8 + 2 * tg;
        *(float2*)&Out[orow0 + c] = make_float2(oacc[nt][0] * r0, oacc[nt][1] * r0);
        *(float2*)&Out[orow1 + c] = make_float2(oacc[nt][2] * r1, oacc[nt][3] * r1);
    }
}

// ---------------- launch ----------------
extern "C" void kernel_launch(void* const* d_in, const int* in_sizes, int n_in,
                              void* d_out, int out_size) {
    const float* x  = (const float*)d_in[0];
    const float* y  = (const float*)d_in[1];
    const unsigned char* ymask = (const unsigned char*)d_in[2];
    const float* Wq = (const float*)d_in[3];
    const float* bq = (const float*)d_in[4];
    const float* Wk = (const float*)d_in[5];
    const float* bk = (const float*)d_in[6];
    const float* Wv = (const float*)d_in[7];
    const float* bv = (const float*)d_in[8];
    float* out = (float*)d_out;

    float *Qp, *Kp, *Vp;
    cudaGetSymbolAddress((void**)&Qp, g_Q);
    cudaGetSymbolAddress((void**)&Kp, g_K);
    cudaGetSymbolAddress((void**)&Vp, g_V);

    mask_canon_kernel<<<1, 256>>>(ymask);

    dim3 pgrid(8, 128);  // (N/128, M/128)
    proj_kernel<<<pgrid, 256>>>(x, Wq, bq, Qp);
    proj_kernel<<<pgrid, 256>>>(y, Wk, bk, Kp);
    proj_kernel<<<pgrid, 256>>>(y, Wv, bv, Vp);

    cudaFuncSetAttribute(attn_kernel, cudaFuncAttributeMaxDynamicSharedMemorySize, ATTN_SMEM_BYTES);
    attn_kernel<<<dim3(L1_ / 128, H_, B_), 256, ATTN_SMEM_BYTES>>>(Qp, Kp, Vp, out);
}